// round 1
// baseline (speedup 1.0000x reference)
#include <cuda_runtime.h>
#include <math.h>

// Problem constants
#define BQ   16
#define NP   2048
#define DF   256
#define NH   8
#define DHD  64
#define KN   8
#define ID   512
#define QKV3 1536
#define RAD2 0.09f
#define LNEPS 1e-5f

// Scratch (static device globals; runtime allocation is forbidden)
__device__ int   g_idx[BQ * NP * KN];
__device__ float g_normed[BQ * NP * DF];
__device__ float g_qkv[BQ * NP * QKV3];
__device__ float g_ao[BQ * NP * ID];

// ---------------------------------------------------------------------------
// Kernel 1: ball_query. One warp handles one query point; per-batch xyz cached
// in shared memory. Collect first KN indices (ascending) with d2 < RAD2,
// pad with the first hit.
// ---------------------------------------------------------------------------
__global__ void __launch_bounds__(256) ball_kernel(const float* __restrict__ xyzs) {
    __shared__ float sx[NP], sy[NP], sz[NP], s2[NP];
    __shared__ int sres[8][KN];
    const int b = blockIdx.y;
    const float* xb = xyzs + (size_t)b * NP * 3;
    for (int i = threadIdx.x; i < NP; i += 256) {
        float x = xb[3 * i], y = xb[3 * i + 1], z = xb[3 * i + 2];
        sx[i] = x; sy[i] = y; sz[i] = z;
        s2[i] = x * x + y * y + z * z;
    }
    __syncthreads();
    const int warp = threadIdx.x >> 5, lane = threadIdx.x & 31;
    for (int qi = 0; qi < 8; qi++) {
        const int n = blockIdx.x * 64 + warp * 8 + qi;
        const float qx = sx[n], qy = sy[n], qz = sz[n], q2 = s2[n];
        int found = 0;
        for (int t = 0; t < NP && found < KN; t += 32) {
            const int m = t + lane;
            float d2 = q2 + s2[m] - 2.0f * (qx * sx[m] + qy * sy[m] + qz * sz[m]);
            unsigned mask = __ballot_sync(0xffffffffu, d2 < RAD2);
            while (mask && found < KN) {
                int bit = __ffs(mask) - 1;
                if (lane == 0) sres[warp][found] = t + bit;
                found++;
                mask &= mask - 1;
            }
        }
        __syncwarp();
        if (lane < KN) {
            int v = sres[warp][lane < found ? lane : 0];
            g_idx[((size_t)b * NP + n) * KN + lane] = v;
        }
        __syncwarp();
    }
}

// ---------------------------------------------------------------------------
// Kernel 2: LayerNorm. One warp per row of 256; each lane owns 8 contiguous.
// ---------------------------------------------------------------------------
__global__ void __launch_bounds__(256) ln_kernel(const float* __restrict__ feature,
                                                 const float* __restrict__ gam,
                                                 const float* __restrict__ bet) {
    const int row = blockIdx.x * 8 + (threadIdx.x >> 5);
    const int lane = threadIdx.x & 31;
    const float* f = feature + (size_t)row * DF + lane * 8;
    float v[8];
    float4 v0 = *(const float4*)f;
    float4 v1 = *(const float4*)(f + 4);
    v[0] = v0.x; v[1] = v0.y; v[2] = v0.z; v[3] = v0.w;
    v[4] = v1.x; v[5] = v1.y; v[6] = v1.z; v[7] = v1.w;
    float s = 0.f;
#pragma unroll
    for (int i = 0; i < 8; i++) s += v[i];
#pragma unroll
    for (int o = 16; o; o >>= 1) s += __shfl_xor_sync(0xffffffffu, s, o);
    const float mu = s * (1.0f / DF);
    float sq = 0.f;
#pragma unroll
    for (int i = 0; i < 8; i++) { float d = v[i] - mu; sq += d * d; }
#pragma unroll
    for (int o = 16; o; o >>= 1) sq += __shfl_xor_sync(0xffffffffu, sq, o);
    const float rs = rsqrtf(sq * (1.0f / DF) + LNEPS);
    const float* gp = gam + lane * 8;
    const float* bp = bet + lane * 8;
    float o[8];
#pragma unroll
    for (int i = 0; i < 8; i++) o[i] = (v[i] - mu) * rs * gp[i] + bp[i];
    float* op = g_normed + (size_t)row * DF + lane * 8;
    float4 w0 = {o[0], o[1], o[2], o[3]};
    float4 w1 = {o[4], o[5], o[6], o[7]};
    *(float4*)op = w0;
    *(float4*)(op + 4) = w1;
}

// ---------------------------------------------------------------------------
// Kernel 3/5: classic 128x128x8 fp32 SGEMM, 256 threads, 8x8 microtiles.
// EPI=0: plain store. EPI=1: +bias, exact GELU, +residual.
// Grid must exactly tile M,N (true here: M=32768; N in {1536, 256}).
// ---------------------------------------------------------------------------
template <int EPI>
__global__ void __launch_bounds__(256) sgemm_kernel(
    const float* __restrict__ A, const float* __restrict__ Bm, float* __restrict__ C,
    int N, int Kd, const float* __restrict__ bias, const float* __restrict__ resid) {
    __shared__ float As[8][128];
    __shared__ float Bs[8][128];
    const int tid = threadIdx.x;
    const int brow = blockIdx.y * 128;
    const int bcol = blockIdx.x * 128;
    const int a_row = tid >> 1;
    const int a_col = (tid & 1) << 2;
    const int b_row = tid >> 5;
    const int b_col = (tid & 31) << 2;
    const int ty = tid >> 4;
    const int tx = tid & 15;
    const float* Ap = A + (size_t)(brow + a_row) * Kd + a_col;
    const float* Bp = Bm + (size_t)b_row * N + bcol + b_col;
    float acc[8][8];
#pragma unroll
    for (int i = 0; i < 8; i++)
#pragma unroll
        for (int j = 0; j < 8; j++) acc[i][j] = 0.f;

    for (int k0 = 0; k0 < Kd; k0 += 8) {
        float4 av = *(const float4*)(Ap + k0);
        float4 bv = *(const float4*)(Bp + (size_t)k0 * N);
        As[a_col + 0][a_row] = av.x;
        As[a_col + 1][a_row] = av.y;
        As[a_col + 2][a_row] = av.z;
        As[a_col + 3][a_row] = av.w;
        *(float4*)&Bs[b_row][b_col] = bv;
        __syncthreads();
#pragma unroll
        for (int kk = 0; kk < 8; kk++) {
            float4 a0 = *(const float4*)&As[kk][ty * 8];
            float4 a1 = *(const float4*)&As[kk][ty * 8 + 4];
            float4 q0 = *(const float4*)&Bs[kk][tx * 8];
            float4 q1 = *(const float4*)&Bs[kk][tx * 8 + 4];
            float ar[8] = {a0.x, a0.y, a0.z, a0.w, a1.x, a1.y, a1.z, a1.w};
            float br[8] = {q0.x, q0.y, q0.z, q0.w, q1.x, q1.y, q1.z, q1.w};
#pragma unroll
            for (int i = 0; i < 8; i++)
#pragma unroll
                for (int j = 0; j < 8; j++) acc[i][j] = fmaf(ar[i], br[j], acc[i][j]);
        }
        __syncthreads();
    }

#pragma unroll
    for (int i = 0; i < 8; i++) {
        const int r = brow + ty * 8 + i;
        const int cbase = bcol + tx * 8;
        float* Cp = C + (size_t)r * N + cbase;
        if (EPI == 0) {
            float4 o0 = {acc[i][0], acc[i][1], acc[i][2], acc[i][3]};
            float4 o1 = {acc[i][4], acc[i][5], acc[i][6], acc[i][7]};
            *(float4*)Cp = o0;
            *(float4*)(Cp + 4) = o1;
        } else {
            const float* rp = resid + (size_t)r * N + cbase;
            float outv[8];
#pragma unroll
            for (int j = 0; j < 8; j++) {
                float x = acc[i][j] + bias[cbase + j];
                float ge = 0.5f * x * (1.0f + erff(x * 0.70710678118654752f));
                outv[j] = ge + rp[j];
            }
            float4 o0 = {outv[0], outv[1], outv[2], outv[3]};
            float4 o1 = {outv[4], outv[5], outv[6], outv[7]};
            *(float4*)Cp = o0;
            *(float4*)(Cp + 4) = o1;
        }
    }
}

// ---------------------------------------------------------------------------
// Kernel 4: attention over K=8 neighbors + spatial op.
// One block (256 threads = 8 warps) per point; warp h handles head h
// (64 dims = lane and lane+32). Writes ao + dis to g_ao.
// ---------------------------------------------------------------------------
__global__ void __launch_bounds__(256) attn_kernel(const float* __restrict__ xyzs,
                                                   const float* __restrict__ w_sp) {
    const int p = blockIdx.x;     // b*NP + n
    const int b = p >> 11;
    const int warp = threadIdx.x >> 5;  // head
    const int lane = threadIdx.x & 31;

    __shared__ int sidx[KN];
    __shared__ float sdisp[KN][3];
    if (threadIdx.x < KN) sidx[threadIdx.x] = g_idx[(size_t)p * KN + threadIdx.x];
    __syncthreads();
    if (threadIdx.x < KN * 3) {
        int j = threadIdx.x / 3, c = threadIdx.x % 3;
        sdisp[j][c] = xyzs[((size_t)b * NP + sidx[j]) * 3 + c] - xyzs[(size_t)p * 3 + c];
    }
    __syncthreads();

    const size_t qoff = (size_t)p * QKV3 + warp * DHD;
    const float qa = g_qkv[qoff + lane];
    const float qb = g_qkv[qoff + 32 + lane];

    float logits[KN];
#pragma unroll
    for (int j = 0; j < KN; j++) {
        const size_t koff = ((size_t)b * NP + sidx[j]) * QKV3 + ID + warp * DHD;
        float d = qa * g_qkv[koff + lane] + qb * g_qkv[koff + 32 + lane];
#pragma unroll
        for (int o = 16; o; o >>= 1) d += __shfl_xor_sync(0xffffffffu, d, o);
        logits[j] = d * 0.125f;  // DH^-0.5
    }

    // softmax over K (computed redundantly by all lanes; values are uniform)
    float mx = logits[0];
#pragma unroll
    for (int j = 1; j < KN; j++) mx = fmaxf(mx, logits[j]);
    float a[KN];
    float se = 0.f;
#pragma unroll
    for (int j = 0; j < KN; j++) { a[j] = expf(logits[j] - mx); se += a[j]; }
    const float inv = 1.0f / se;
#pragma unroll
    for (int j = 0; j < KN; j++) a[j] *= inv;

    // attn @ V
    float oa = 0.f, ob = 0.f;
#pragma unroll
    for (int j = 0; j < KN; j++) {
        const size_t voff = ((size_t)b * NP + sidx[j]) * QKV3 + 2 * ID + warp * DHD;
        oa = fmaf(a[j], g_qkv[voff + lane], oa);
        ob = fmaf(a[j], g_qkv[voff + 32 + lane], ob);
    }

    // dis = max_j(a_j * disp_j) per coordinate, then @ w_sp [3,64]
    float dm[3];
#pragma unroll
    for (int c = 0; c < 3; c++) {
        float m = a[0] * sdisp[0][c];
#pragma unroll
        for (int j = 1; j < KN; j++) m = fmaxf(m, a[j] * sdisp[j][c]);
        dm[c] = m;
    }
    const float da = dm[0] * w_sp[lane] + dm[1] * w_sp[64 + lane] + dm[2] * w_sp[128 + lane];
    const float db = dm[0] * w_sp[32 + lane] + dm[1] * w_sp[96 + lane] + dm[2] * w_sp[160 + lane];

    float* op = g_ao + (size_t)p * ID + warp * DHD;
    op[lane] = oa + da;
    op[32 + lane] = ob + db;
}

// ---------------------------------------------------------------------------
extern "C" void kernel_launch(void* const* d_in, const int* in_sizes, int n_in,
                              void* d_out, int out_size) {
    (void)in_sizes; (void)n_in; (void)out_size;
    const float* xyzs    = (const float*)d_in[0];
    const float* feature = (const float*)d_in[1];
    const float* ln_g    = (const float*)d_in[2];
    const float* ln_b    = (const float*)d_in[3];
    const float* w_qkv   = (const float*)d_in[4];
    const float* w_sp    = (const float*)d_in[5];
    const float* w_out   = (const float*)d_in[6];
    const float* b_out   = (const float*)d_in[7];
    float* out = (float*)d_out;

    void* p_normed = nullptr; void* p_qkv = nullptr; void* p_ao = nullptr;
    cudaGetSymbolAddress(&p_normed, g_normed);
    cudaGetSymbolAddress(&p_qkv, g_qkv);
    cudaGetSymbolAddress(&p_ao, g_ao);
    float* normed = (float*)p_normed;
    float* qkv = (float*)p_qkv;
    float* ao = (float*)p_ao;

    // 1) ball query
    ball_kernel<<<dim3(NP / 64, BQ), 256>>>(xyzs);
    // 2) layernorm
    ln_kernel<<<(BQ * NP) / 8, 256>>>(feature, ln_g, ln_b);
    // 3) qkv = normed @ w_qkv   [32768 x 256] @ [256 x 1536]
    sgemm_kernel<0><<<dim3(QKV3 / 128, (BQ * NP) / 128), 256>>>(
        normed, w_qkv, qkv, QKV3, DF, nullptr, nullptr);
    // 4) attention + spatial op -> g_ao
    attn_kernel<<<BQ * NP, 256>>>(xyzs, w_sp);
    // 5) out = gelu(ao @ w_out + b_out) + feature   [32768 x 512] @ [512 x 256]
    sgemm_kernel<1><<<dim3(DF / 128, (BQ * NP) / 128), 256>>>(
        ao, w_out, out, DF, ID, b_out, feature);
}

// round 2
// speedup vs baseline: 1.5220x; 1.5220x over previous
#include <cuda_runtime.h>
#include <math.h>
#include <stdint.h>

// Problem constants
#define BQ   16
#define NP   2048
#define DF   256
#define NH   8
#define DHD  64
#define KN   8
#define ID   512
#define QKV3 1536
#define RAD2 0.09f
#define LNEPS 1e-5f

// Scratch (static device globals; runtime allocation is forbidden)
__device__ int   g_idx[BQ * NP * KN];
__device__ float g_normed[BQ * NP * DF];
__device__ float g_qkv[BQ * NP * QKV3];
__device__ float g_ao[BQ * NP * ID];

// ---------------------------------------------------------------------------
// PTX helpers
// ---------------------------------------------------------------------------
__device__ __forceinline__ uint32_t f2tf32(float x) {
    uint32_t u;
    asm("cvt.rna.tf32.f32 %0, %1;" : "=r"(u) : "f"(x));
    return u;
}

__device__ __forceinline__ void mma_tf32(float* c, const uint32_t* a, const uint32_t* b) {
    asm volatile(
        "mma.sync.aligned.m16n8k8.row.col.f32.tf32.tf32.f32 "
        "{%0,%1,%2,%3}, {%4,%5,%6,%7}, {%8,%9}, {%0,%1,%2,%3};"
        : "+f"(c[0]), "+f"(c[1]), "+f"(c[2]), "+f"(c[3])
        : "r"(a[0]), "r"(a[1]), "r"(a[2]), "r"(a[3]), "r"(b[0]), "r"(b[1]));
}

__device__ __forceinline__ void cp16(uint32_t smem_dst, const void* gsrc) {
    asm volatile("cp.async.cg.shared.global [%0], [%1], 16;" :: "r"(smem_dst), "l"(gsrc));
}
__device__ __forceinline__ void cp_commit() { asm volatile("cp.async.commit_group;"); }
template <int N>
__device__ __forceinline__ void cp_wait() { asm volatile("cp.async.wait_group %0;" :: "n"(N)); }

// ---------------------------------------------------------------------------
// Kernel 1: ball_query (unchanged)
// ---------------------------------------------------------------------------
__global__ void __launch_bounds__(256) ball_kernel(const float* __restrict__ xyzs) {
    __shared__ float sx[NP], sy[NP], sz[NP], s2[NP];
    __shared__ int sres[8][KN];
    const int b = blockIdx.y;
    const float* xb = xyzs + (size_t)b * NP * 3;
    for (int i = threadIdx.x; i < NP; i += 256) {
        float x = xb[3 * i], y = xb[3 * i + 1], z = xb[3 * i + 2];
        sx[i] = x; sy[i] = y; sz[i] = z;
        s2[i] = x * x + y * y + z * z;
    }
    __syncthreads();
    const int warp = threadIdx.x >> 5, lane = threadIdx.x & 31;
    for (int qi = 0; qi < 8; qi++) {
        const int n = blockIdx.x * 64 + warp * 8 + qi;
        const float qx = sx[n], qy = sy[n], qz = sz[n], q2 = s2[n];
        int found = 0;
        for (int t = 0; t < NP && found < KN; t += 32) {
            const int m = t + lane;
            float d2 = q2 + s2[m] - 2.0f * (qx * sx[m] + qy * sy[m] + qz * sz[m]);
            unsigned mask = __ballot_sync(0xffffffffu, d2 < RAD2);
            while (mask && found < KN) {
                int bit = __ffs(mask) - 1;
                if (lane == 0) sres[warp][found] = t + bit;
                found++;
                mask &= mask - 1;
            }
        }
        __syncwarp();
        if (lane < KN) {
            int v = sres[warp][lane < found ? lane : 0];
            g_idx[((size_t)b * NP + n) * KN + lane] = v;
        }
        __syncwarp();
    }
}

// ---------------------------------------------------------------------------
// Kernel 2: LayerNorm (unchanged)
// ---------------------------------------------------------------------------
__global__ void __launch_bounds__(256) ln_kernel(const float* __restrict__ feature,
                                                 const float* __restrict__ gam,
                                                 const float* __restrict__ bet) {
    const int row = blockIdx.x * 8 + (threadIdx.x >> 5);
    const int lane = threadIdx.x & 31;
    const float* f = feature + (size_t)row * DF + lane * 8;
    float v[8];
    float4 v0 = *(const float4*)f;
    float4 v1 = *(const float4*)(f + 4);
    v[0] = v0.x; v[1] = v0.y; v[2] = v0.z; v[3] = v0.w;
    v[4] = v1.x; v[5] = v1.y; v[6] = v1.z; v[7] = v1.w;
    float s = 0.f;
#pragma unroll
    for (int i = 0; i < 8; i++) s += v[i];
#pragma unroll
    for (int o = 16; o; o >>= 1) s += __shfl_xor_sync(0xffffffffu, s, o);
    const float mu = s * (1.0f / DF);
    float sq = 0.f;
#pragma unroll
    for (int i = 0; i < 8; i++) { float d = v[i] - mu; sq += d * d; }
#pragma unroll
    for (int o = 16; o; o >>= 1) sq += __shfl_xor_sync(0xffffffffu, sq, o);
    const float rs = rsqrtf(sq * (1.0f / DF) + LNEPS);
    const float* gp = gam + lane * 8;
    const float* bp = bet + lane * 8;
    float o[8];
#pragma unroll
    for (int i = 0; i < 8; i++) o[i] = (v[i] - mu) * rs * gp[i] + bp[i];
    float* op = g_normed + (size_t)row * DF + lane * 8;
    float4 w0 = {o[0], o[1], o[2], o[3]};
    float4 w1 = {o[4], o[5], o[6], o[7]};
    *(float4*)op = w0;
    *(float4*)(op + 4) = w1;
}

// ---------------------------------------------------------------------------
// Kernel 3/5: tf32 tensor-core GEMM. 128x128 block tile, ktile 32, 8 warps
// (4x2), each warp 32x64 via m16n8k8 mma. cp.async double-buffered smem.
//   As: [row][k] stride 36 (pad 4)  -> conflict-free fragment LDS
//   Bs: [k][n]  stride 132 (pad 4)  -> conflict-free fragment LDS
// EPI=0: plain store. EPI=1: +bias, exact GELU, +residual.
// Requires M%128==0, N%128==0, K%32==0 (true here).
// ---------------------------------------------------------------------------
#define AS_STRIDE 36
#define BS_STRIDE 132
#define AS_FLOATS (128 * AS_STRIDE)
#define BS_FLOATS (32 * BS_STRIDE)
#define GEMM_SMEM_BYTES ((2 * AS_FLOATS + 2 * BS_FLOATS) * 4)

template <int EPI>
__global__ void __launch_bounds__(256) tgemm_kernel(
    const float* __restrict__ A, const float* __restrict__ Bm, float* __restrict__ C,
    int N, int Kd, const float* __restrict__ bias, const float* __restrict__ resid) {
    extern __shared__ float smem[];
    float* AsBuf[2] = {smem, smem + AS_FLOATS};
    float* BsBuf[2] = {smem + 2 * AS_FLOATS, smem + 2 * AS_FLOATS + BS_FLOATS};

    const int tid = threadIdx.x;
    const int warp = tid >> 5, lane = tid & 31;
    const int warp_m = warp >> 1, warp_n = warp & 1;
    const int brow = blockIdx.y * 128;
    const int bcol = blockIdx.x * 128;
    const int KT = Kd / 32;

    // copy-index precompute
    const int a_r0 = tid >> 3;          // 0..31
    const int a_c = (tid & 7) * 4;      // 0..28
    const int b_r0 = tid >> 5;          // 0..7
    const int b_c = (tid & 31) * 4;     // 0..124

    auto load_tile = [&](int kt, int buf) {
        const uint32_t as_base = (uint32_t)__cvta_generic_to_shared(AsBuf[buf]);
        const uint32_t bs_base = (uint32_t)__cvta_generic_to_shared(BsBuf[buf]);
#pragma unroll
        for (int i = 0; i < 4; i++) {
            const int row = a_r0 + 32 * i;
            cp16(as_base + (row * AS_STRIDE + a_c) * 4,
                 A + (size_t)(brow + row) * Kd + kt * 32 + a_c);
        }
#pragma unroll
        for (int i = 0; i < 4; i++) {
            const int row = b_r0 + 8 * i;
            cp16(bs_base + (row * BS_STRIDE + b_c) * 4,
                 Bm + (size_t)(kt * 32 + row) * N + bcol + b_c);
        }
        cp_commit();
    };

    float acc[2][8][4];
#pragma unroll
    for (int mt = 0; mt < 2; mt++)
#pragma unroll
        for (int nt = 0; nt < 8; nt++)
#pragma unroll
            for (int r = 0; r < 4; r++) acc[mt][nt][r] = 0.f;

    load_tile(0, 0);

    const int lg = lane >> 2;   // 0..7
    const int lt = lane & 3;    // 0..3

    for (int kt = 0; kt < KT; kt++) {
        const int buf = kt & 1;
        if (kt + 1 < KT) {
            load_tile(kt + 1, buf ^ 1);
            cp_wait<1>();
        } else {
            cp_wait<0>();
        }
        __syncthreads();

        const float* As = AsBuf[buf];
        const float* Bs = BsBuf[buf];
#pragma unroll
        for (int ks = 0; ks < 4; ks++) {
            const int k0 = ks * 8 + lt;
            uint32_t af[2][4], bf[8][2];
#pragma unroll
            for (int mt = 0; mt < 2; mt++) {
                const int r0 = warp_m * 32 + mt * 16 + lg;
                af[mt][0] = f2tf32(As[r0 * AS_STRIDE + k0]);
                af[mt][1] = f2tf32(As[(r0 + 8) * AS_STRIDE + k0]);
                af[mt][2] = f2tf32(As[r0 * AS_STRIDE + k0 + 4]);
                af[mt][3] = f2tf32(As[(r0 + 8) * AS_STRIDE + k0 + 4]);
            }
#pragma unroll
            for (int nt = 0; nt < 8; nt++) {
                const int n0 = warp_n * 64 + nt * 8 + lg;
                bf[nt][0] = f2tf32(Bs[k0 * BS_STRIDE + n0]);
                bf[nt][1] = f2tf32(Bs[(k0 + 4) * BS_STRIDE + n0]);
            }
#pragma unroll
            for (int mt = 0; mt < 2; mt++)
#pragma unroll
                for (int nt = 0; nt < 8; nt++)
                    mma_tf32(acc[mt][nt], af[mt], bf[nt]);
        }
        __syncthreads();
    }

    // Epilogue
#pragma unroll
    for (int mt = 0; mt < 2; mt++) {
#pragma unroll
        for (int nt = 0; nt < 8; nt++) {
            const int r = brow + warp_m * 32 + mt * 16 + lg;
            const int c = bcol + warp_n * 64 + nt * 8 + 2 * lt;
#pragma unroll
            for (int h = 0; h < 2; h++) {   // row r, row r+8
                const int rr = r + h * 8;
                float x0 = acc[mt][nt][h * 2 + 0];
                float x1 = acc[mt][nt][h * 2 + 1];
                float* Cp = C + (size_t)rr * N + c;
                if (EPI == 0) {
                    float2 o = {x0, x1};
                    *(float2*)Cp = o;
                } else {
                    const float* rp = resid + (size_t)rr * N + c;
                    float a0 = x0 + bias[c];
                    float a1 = x1 + bias[c + 1];
                    float g0 = 0.5f * a0 * (1.0f + erff(a0 * 0.70710678118654752f));
                    float g1 = 0.5f * a1 * (1.0f + erff(a1 * 0.70710678118654752f));
                    float2 o = {g0 + rp[0], g1 + rp[1]};
                    *(float2*)Cp = o;
                }
            }
        }
    }
}

// ---------------------------------------------------------------------------
// Kernel 4: attention over K=8 neighbors + spatial op (unchanged)
// ---------------------------------------------------------------------------
__global__ void __launch_bounds__(256) attn_kernel(const float* __restrict__ xyzs,
                                                   const float* __restrict__ w_sp) {
    const int p = blockIdx.x;     // b*NP + n
    const int b = p >> 11;
    const int warp = threadIdx.x >> 5;  // head
    const int lane = threadIdx.x & 31;

    __shared__ int sidx[KN];
    __shared__ float sdisp[KN][3];
    if (threadIdx.x < KN) sidx[threadIdx.x] = g_idx[(size_t)p * KN + threadIdx.x];
    __syncthreads();
    if (threadIdx.x < KN * 3) {
        int j = threadIdx.x / 3, c = threadIdx.x % 3;
        sdisp[j][c] = xyzs[((size_t)b * NP + sidx[j]) * 3 + c] - xyzs[(size_t)p * 3 + c];
    }
    __syncthreads();

    const size_t qoff = (size_t)p * QKV3 + warp * DHD;
    const float qa = g_qkv[qoff + lane];
    const float qb = g_qkv[qoff + 32 + lane];

    float logits[KN];
#pragma unroll
    for (int j = 0; j < KN; j++) {
        const size_t koff = ((size_t)b * NP + sidx[j]) * QKV3 + ID + warp * DHD;
        float d = qa * g_qkv[koff + lane] + qb * g_qkv[koff + 32 + lane];
#pragma unroll
        for (int o = 16; o; o >>= 1) d += __shfl_xor_sync(0xffffffffu, d, o);
        logits[j] = d * 0.125f;  // DH^-0.5
    }

    float mx = logits[0];
#pragma unroll
    for (int j = 1; j < KN; j++) mx = fmaxf(mx, logits[j]);
    float a[KN];
    float se = 0.f;
#pragma unroll
    for (int j = 0; j < KN; j++) { a[j] = expf(logits[j] - mx); se += a[j]; }
    const float inv = 1.0f / se;
#pragma unroll
    for (int j = 0; j < KN; j++) a[j] *= inv;

    float oa = 0.f, ob = 0.f;
#pragma unroll
    for (int j = 0; j < KN; j++) {
        const size_t voff = ((size_t)b * NP + sidx[j]) * QKV3 + 2 * ID + warp * DHD;
        oa = fmaf(a[j], g_qkv[voff + lane], oa);
        ob = fmaf(a[j], g_qkv[voff + 32 + lane], ob);
    }

    float dm[3];
#pragma unroll
    for (int c = 0; c < 3; c++) {
        float m = a[0] * sdisp[0][c];
#pragma unroll
        for (int j = 1; j < KN; j++) m = fmaxf(m, a[j] * sdisp[j][c]);
        dm[c] = m;
    }
    const float da = dm[0] * w_sp[lane] + dm[1] * w_sp[64 + lane] + dm[2] * w_sp[128 + lane];
    const float db = dm[0] * w_sp[32 + lane] + dm[1] * w_sp[96 + lane] + dm[2] * w_sp[160 + lane];

    float* op = g_ao + (size_t)p * ID + warp * DHD;
    op[lane] = oa + da;
    op[32 + lane] = ob + db;
}

// ---------------------------------------------------------------------------
extern "C" void kernel_launch(void* const* d_in, const int* in_sizes, int n_in,
                              void* d_out, int out_size) {
    (void)in_sizes; (void)n_in; (void)out_size;
    const float* xyzs    = (const float*)d_in[0];
    const float* feature = (const float*)d_in[1];
    const float* ln_g    = (const float*)d_in[2];
    const float* ln_b    = (const float*)d_in[3];
    const float* w_qkv   = (const float*)d_in[4];
    const float* w_sp    = (const float*)d_in[5];
    const float* w_out   = (const float*)d_in[6];
    const float* b_out   = (const float*)d_in[7];
    float* out = (float*)d_out;

    void* p_normed = nullptr; void* p_qkv = nullptr; void* p_ao = nullptr;
    cudaGetSymbolAddress(&p_normed, g_normed);
    cudaGetSymbolAddress(&p_qkv, g_qkv);
    cudaGetSymbolAddress(&p_ao, g_ao);
    float* normed = (float*)p_normed;
    float* qkv = (float*)p_qkv;
    float* ao = (float*)p_ao;

    cudaFuncSetAttribute(tgemm_kernel<0>, cudaFuncAttributeMaxDynamicSharedMemorySize,
                         GEMM_SMEM_BYTES);
    cudaFuncSetAttribute(tgemm_kernel<1>, cudaFuncAttributeMaxDynamicSharedMemorySize,
                         GEMM_SMEM_BYTES);

    // 1) ball query
    ball_kernel<<<dim3(NP / 64, BQ), 256>>>(xyzs);
    // 2) layernorm
    ln_kernel<<<(BQ * NP) / 8, 256>>>(feature, ln_g, ln_b);
    // 3) qkv = normed @ w_qkv   [32768 x 256] @ [256 x 1536]
    tgemm_kernel<0><<<dim3(QKV3 / 128, (BQ * NP) / 128), 256, GEMM_SMEM_BYTES>>>(
        normed, w_qkv, qkv, QKV3, DF, nullptr, nullptr);
    // 4) attention + spatial op -> g_ao
    attn_kernel<<<BQ * NP, 256>>>(xyzs, w_sp);
    // 5) out = gelu(ao @ w_out + b_out) + feature   [32768 x 512] @ [512 x 256]
    tgemm_kernel<1><<<dim3(DF / 128, (BQ * NP) / 128), 256, GEMM_SMEM_BYTES>>>(
        ao, w_out, out, DF, ID, b_out, feature);
}

// round 4
// speedup vs baseline: 2.8066x; 1.8440x over previous
#include <cuda_runtime.h>
#include <cuda_fp16.h>
#include <math.h>
#include <stdint.h>

// Problem constants
#define BQ   16
#define NP   2048
#define DF   256
#define NH   8
#define DHD  64
#define KN   8
#define ID   512
#define QKV3 1536
#define RAD2 0.09f
#define LNEPS 1e-5f

// Scratch (static device globals; runtime allocation is forbidden)
__device__ int    g_idx[BQ * NP * KN];
__device__ __half g_normed_h[BQ * NP * DF];
__device__ __half g_qkv_h[BQ * NP * QKV3];
__device__ __half g_ao_h[BQ * NP * ID];
__device__ __half g_wqkv_h[DF * QKV3];
__device__ __half g_wout_h[ID * DF];

// ---------------------------------------------------------------------------
// PTX helpers
// ---------------------------------------------------------------------------
__device__ __forceinline__ void mma_f16(float* c, const uint32_t* a, const uint32_t* b) {
    asm volatile(
        "mma.sync.aligned.m16n8k16.row.col.f32.f16.f16.f32 "
        "{%0,%1,%2,%3}, {%4,%5,%6,%7}, {%8,%9}, {%0,%1,%2,%3};"
        : "+f"(c[0]), "+f"(c[1]), "+f"(c[2]), "+f"(c[3])
        : "r"(a[0]), "r"(a[1]), "r"(a[2]), "r"(a[3]), "r"(b[0]), "r"(b[1]));
}

__device__ __forceinline__ void ldsm_x4(uint32_t& r0, uint32_t& r1, uint32_t& r2,
                                        uint32_t& r3, uint32_t addr) {
    asm volatile("ldmatrix.sync.aligned.m8n8.x4.shared.b16 {%0,%1,%2,%3}, [%4];"
                 : "=r"(r0), "=r"(r1), "=r"(r2), "=r"(r3) : "r"(addr));
}
__device__ __forceinline__ void ldsm_x4t(uint32_t& r0, uint32_t& r1, uint32_t& r2,
                                         uint32_t& r3, uint32_t addr) {
    asm volatile("ldmatrix.sync.aligned.m8n8.x4.trans.shared.b16 {%0,%1,%2,%3}, [%4];"
                 : "=r"(r0), "=r"(r1), "=r"(r2), "=r"(r3) : "r"(addr));
}

__device__ __forceinline__ void cp16(uint32_t smem_dst, const void* gsrc) {
    asm volatile("cp.async.cg.shared.global [%0], [%1], 16;" :: "r"(smem_dst), "l"(gsrc));
}
__device__ __forceinline__ void cp_commit() { asm volatile("cp.async.commit_group;"); }
template <int N>
__device__ __forceinline__ void cp_wait() { asm volatile("cp.async.wait_group %0;" :: "n"(N)); }

// ---------------------------------------------------------------------------
// Kernel 1: ball_query
// ---------------------------------------------------------------------------
__global__ void __launch_bounds__(256) ball_kernel(const float* __restrict__ xyzs) {
    __shared__ float sx[NP], sy[NP], sz[NP], s2[NP];
    __shared__ int sres[8][KN];
    const int b = blockIdx.y;
    const float* xb = xyzs + (size_t)b * NP * 3;
    for (int i = threadIdx.x; i < NP; i += 256) {
        float x = xb[3 * i], y = xb[3 * i + 1], z = xb[3 * i + 2];
        sx[i] = x; sy[i] = y; sz[i] = z;
        s2[i] = x * x + y * y + z * z;
    }
    __syncthreads();
    const int warp = threadIdx.x >> 5, lane = threadIdx.x & 31;
    for (int qi = 0; qi < 8; qi++) {
        const int n = blockIdx.x * 64 + warp * 8 + qi;
        const float qx = sx[n], qy = sy[n], qz = sz[n], q2 = s2[n];
        int found = 0;
        for (int t = 0; t < NP && found < KN; t += 32) {
            const int m = t + lane;
            float d2 = q2 + s2[m] - 2.0f * (qx * sx[m] + qy * sy[m] + qz * sz[m]);
            unsigned mask = __ballot_sync(0xffffffffu, d2 < RAD2);
            while (mask && found < KN) {
                int bit = __ffs(mask) - 1;
                if (lane == 0) sres[warp][found] = t + bit;
                found++;
                mask &= mask - 1;
            }
        }
        __syncwarp();
        if (lane < KN) {
            int v = sres[warp][lane < found ? lane : 0];
            g_idx[((size_t)b * NP + n) * KN + lane] = v;
        }
        __syncwarp();
    }
}

// ---------------------------------------------------------------------------
// Kernel 2: LayerNorm -> fp16 output
// ---------------------------------------------------------------------------
__global__ void __launch_bounds__(256) ln_kernel(const float* __restrict__ feature,
                                                 const float* __restrict__ gam,
                                                 const float* __restrict__ bet) {
    const int row = blockIdx.x * 8 + (threadIdx.x >> 5);
    const int lane = threadIdx.x & 31;
    const float* f = feature + (size_t)row * DF + lane * 8;
    float v[8];
    float4 v0 = *(const float4*)f;
    float4 v1 = *(const float4*)(f + 4);
    v[0] = v0.x; v[1] = v0.y; v[2] = v0.z; v[3] = v0.w;
    v[4] = v1.x; v[5] = v1.y; v[6] = v1.z; v[7] = v1.w;
    float s = 0.f;
#pragma unroll
    for (int i = 0; i < 8; i++) s += v[i];
#pragma unroll
    for (int o = 16; o; o >>= 1) s += __shfl_xor_sync(0xffffffffu, s, o);
    const float mu = s * (1.0f / DF);
    float sq = 0.f;
#pragma unroll
    for (int i = 0; i < 8; i++) { float d = v[i] - mu; sq += d * d; }
#pragma unroll
    for (int o = 16; o; o >>= 1) sq += __shfl_xor_sync(0xffffffffu, sq, o);
    const float rs = rsqrtf(sq * (1.0f / DF) + LNEPS);
    const float* gp = gam + lane * 8;
    const float* bp = bet + lane * 8;
    __half2 o[4];
#pragma unroll
    for (int i = 0; i < 4; i++) {
        float a = (v[2 * i] - mu) * rs * gp[2 * i] + bp[2 * i];
        float bvl = (v[2 * i + 1] - mu) * rs * gp[2 * i + 1] + bp[2 * i + 1];
        o[i] = __floats2half2_rn(a, bvl);
    }
    __half2* op = (__half2*)(g_normed_h + (size_t)row * DF + lane * 8);
#pragma unroll
    for (int i = 0; i < 4; i++) op[i] = o[i];
}

// ---------------------------------------------------------------------------
// Weight conversion fp32 -> fp16
// ---------------------------------------------------------------------------
__global__ void __launch_bounds__(256) conv_kernel(const float* __restrict__ src,
                                                   __half* __restrict__ dst) {
    const int i = (blockIdx.x * 256 + threadIdx.x) * 4;
    float4 v = *(const float4*)(src + i);
    __half2* d = (__half2*)(dst + i);
    d[0] = __floats2half2_rn(v.x, v.y);
    d[1] = __floats2half2_rn(v.z, v.w);
}

// ---------------------------------------------------------------------------
// Kernel 3/5: fp16 tensor-core GEMM, fp32 accumulate.
// 128x128 block tile, ktile 32, 8 warps (4x2), each warp 32x64 via m16n8k16.
// cp.async double-buffered.  As: [128][40] halves.  Bs: [32][136] halves.
// EPI=0: fp16 store. EPI=1: +bias, exact GELU, +fp32 residual, fp32 store.
// Requires M%128==0, N%128==0, K%32==0.
// ---------------------------------------------------------------------------
#define ASH 40
#define BSH 136

template <int EPI>
__global__ void __launch_bounds__(256) hgemm_kernel(
    const __half* __restrict__ A, const __half* __restrict__ Bm, void* __restrict__ Cv,
    int N, int Kd, const float* __restrict__ bias, const float* __restrict__ resid) {
    __shared__ __half As[2][128 * ASH];
    __shared__ __half Bs[2][32 * BSH];

    const int tid = threadIdx.x;
    const int warp = tid >> 5, lane = tid & 31;
    const int warp_m = warp >> 1, warp_n = warp & 1;
    const int brow = blockIdx.y * 128;
    const int bcol = blockIdx.x * 128;
    const int KT = Kd / 32;

    const int a_r0 = tid >> 2;        // 0..63
    const int a_c = (tid & 3) * 8;    // halves 0..24
    const int b_r0 = tid >> 4;        // 0..15
    const int b_c = (tid & 15) * 8;   // halves 0..120

    auto load_tile = [&](int kt, int buf) {
        const uint32_t as_base = (uint32_t)__cvta_generic_to_shared(&As[buf][0]);
        const uint32_t bs_base = (uint32_t)__cvta_generic_to_shared(&Bs[buf][0]);
#pragma unroll
        for (int i = 0; i < 2; i++) {
            const int row = a_r0 + 64 * i;
            cp16(as_base + (row * ASH + a_c) * 2,
                 A + (size_t)(brow + row) * Kd + kt * 32 + a_c);
        }
#pragma unroll
        for (int i = 0; i < 2; i++) {
            const int row = b_r0 + 16 * i;
            cp16(bs_base + (row * BSH + b_c) * 2,
                 Bm + (size_t)(kt * 32 + row) * N + bcol + b_c);
        }
        cp_commit();
    };

    float acc[2][8][4];
#pragma unroll
    for (int mt = 0; mt < 2; mt++)
#pragma unroll
        for (int nt = 0; nt < 8; nt++)
#pragma unroll
            for (int r = 0; r < 4; r++) acc[mt][nt][r] = 0.f;

    load_tile(0, 0);

    const int lg = lane >> 2;   // 0..7
    const int lt = lane & 3;    // 0..3

    // ldmatrix lane addressing (constant per thread)
    const int a_lrow = (lane & 15);
    const int a_lcol = ((lane >> 4) << 3);
    const int b_lk = (lane & 7) + ((lane >> 3) & 1) * 8;
    const int b_ln = ((lane >> 4) << 3);

    for (int kt = 0; kt < KT; kt++) {
        const int buf = kt & 1;
        if (kt + 1 < KT) {
            load_tile(kt + 1, buf ^ 1);
            cp_wait<1>();
        } else {
            cp_wait<0>();
        }
        __syncthreads();

        const uint32_t as_u = (uint32_t)__cvta_generic_to_shared(&As[buf][0]);
        const uint32_t bs_u = (uint32_t)__cvta_generic_to_shared(&Bs[buf][0]);

#pragma unroll
        for (int ks = 0; ks < 2; ks++) {
            uint32_t af[2][4], bf[8][2];
#pragma unroll
            for (int mt = 0; mt < 2; mt++) {
                const int row = warp_m * 32 + mt * 16 + a_lrow;
                const int col = ks * 16 + a_lcol;
                ldsm_x4(af[mt][0], af[mt][1], af[mt][2], af[mt][3],
                        as_u + (row * ASH + col) * 2);
            }
#pragma unroll
            for (int np = 0; np < 4; np++) {
                const int k = ks * 16 + b_lk;
                const int n = warp_n * 64 + np * 16 + b_ln;
                ldsm_x4t(bf[2 * np][0], bf[2 * np][1], bf[2 * np + 1][0], bf[2 * np + 1][1],
                         bs_u + (k * BSH + n) * 2);
            }
#pragma unroll
            for (int mt = 0; mt < 2; mt++)
#pragma unroll
                for (int nt = 0; nt < 8; nt++)
                    mma_f16(acc[mt][nt], af[mt], bf[nt]);
        }
        __syncthreads();
    }

    // Epilogue
#pragma unroll
    for (int mt = 0; mt < 2; mt++) {
#pragma unroll
        for (int nt = 0; nt < 8; nt++) {
            const int r = brow + warp_m * 32 + mt * 16 + lg;
            const int c = bcol + warp_n * 64 + nt * 8 + 2 * lt;
#pragma unroll
            for (int h = 0; h < 2; h++) {
                const int rr = r + h * 8;
                float x0 = acc[mt][nt][h * 2 + 0];
                float x1 = acc[mt][nt][h * 2 + 1];
                if (EPI == 0) {
                    __half* C = (__half*)Cv;
                    *(__half2*)(C + (size_t)rr * N + c) = __floats2half2_rn(x0, x1);
                } else {
                    float* C = (float*)Cv;
                    const float* rp = resid + (size_t)rr * N + c;
                    float a0 = x0 + bias[c];
                    float a1 = x1 + bias[c + 1];
                    float g0 = 0.5f * a0 * (1.0f + erff(a0 * 0.70710678118654752f));
                    float g1 = 0.5f * a1 * (1.0f + erff(a1 * 0.70710678118654752f));
                    float2 o = {g0 + rp[0], g1 + rp[1]};
                    *(float2*)(C + (size_t)rr * N + c) = o;
                }
            }
        }
    }
}

// ---------------------------------------------------------------------------
// Kernel 4: attention over K=8 neighbors + spatial op, fp16 q/k/v.
// One block per point; warp h = head h; lane covers dims (2lane, 2lane+1).
// ---------------------------------------------------------------------------
__global__ void __launch_bounds__(256) attn_kernel(const float* __restrict__ xyzs,
                                                   const float* __restrict__ w_sp) {
    const int p = blockIdx.x;     // b*NP + n
    const int b = p >> 11;
    const int warp = threadIdx.x >> 5;  // head
    const int lane = threadIdx.x & 31;

    __shared__ int sidx[KN];
    __shared__ float sdisp[KN][3];
    if (threadIdx.x < KN) sidx[threadIdx.x] = g_idx[(size_t)p * KN + threadIdx.x];
    __syncthreads();
    if (threadIdx.x < KN * 3) {
        int j = threadIdx.x / 3, c = threadIdx.x % 3;
        sdisp[j][c] = xyzs[((size_t)b * NP + sidx[j]) * 3 + c] - xyzs[(size_t)p * 3 + c];
    }
    __syncthreads();

    const size_t qoff = (size_t)p * QKV3 + warp * DHD + 2 * lane;
    const __half2 q2 = *(const __half2*)(g_qkv_h + qoff);
    const float qx = __low2float(q2), qy = __high2float(q2);

    float logits[KN];
#pragma unroll
    for (int j = 0; j < KN; j++) {
        const size_t koff = ((size_t)b * NP + sidx[j]) * QKV3 + ID + warp * DHD + 2 * lane;
        const __half2 k2 = *(const __half2*)(g_qkv_h + koff);
        float d = qx * __low2float(k2) + qy * __high2float(k2);
#pragma unroll
        for (int o = 16; o; o >>= 1) d += __shfl_xor_sync(0xffffffffu, d, o);
        logits[j] = d * 0.125f;
    }

    float mx = logits[0];
#pragma unroll
    for (int j = 1; j < KN; j++) mx = fmaxf(mx, logits[j]);
    float a[KN];
    float se = 0.f;
#pragma unroll
    for (int j = 0; j < KN; j++) { a[j] = expf(logits[j] - mx); se += a[j]; }
    const float inv = 1.0f / se;
#pragma unroll
    for (int j = 0; j < KN; j++) a[j] *= inv;

    float oa = 0.f, ob = 0.f;
#pragma unroll
    for (int j = 0; j < KN; j++) {
        const size_t voff = ((size_t)b * NP + sidx[j]) * QKV3 + 2 * ID + warp * DHD + 2 * lane;
        const __half2 v2 = *(const __half2*)(g_qkv_h + voff);
        oa = fmaf(a[j], __low2float(v2), oa);
        ob = fmaf(a[j], __high2float(v2), ob);
    }

    float dm[3];
#pragma unroll
    for (int c = 0; c < 3; c++) {
        float m = a[0] * sdisp[0][c];
#pragma unroll
        for (int j = 1; j < KN; j++) m = fmaxf(m, a[j] * sdisp[j][c]);
        dm[c] = m;
    }
    const int d0 = 2 * lane, d1 = 2 * lane + 1;
    const float da = dm[0] * w_sp[d0] + dm[1] * w_sp[64 + d0] + dm[2] * w_sp[128 + d0];
    const float db = dm[0] * w_sp[d1] + dm[1] * w_sp[64 + d1] + dm[2] * w_sp[128 + d1];

    __half2* op = (__half2*)(g_ao_h + (size_t)p * ID + warp * DHD + 2 * lane);
    *op = __floats2half2_rn(oa + da, ob + db);
}

// ---------------------------------------------------------------------------
extern "C" void kernel_launch(void* const* d_in, const int* in_sizes, int n_in,
                              void* d_out, int out_size) {
    (void)in_sizes; (void)n_in; (void)out_size;
    const float* xyzs    = (const float*)d_in[0];
    const float* feature = (const float*)d_in[1];
    const float* ln_g    = (const float*)d_in[2];
    const float* ln_b    = (const float*)d_in[3];
    const float* w_qkv   = (const float*)d_in[4];
    const float* w_sp    = (const float*)d_in[5];
    const float* w_out   = (const float*)d_in[6];
    const float* b_out   = (const float*)d_in[7];
    float* out = (float*)d_out;

    void *p_normed, *p_qkv, *p_ao, *p_wqkv, *p_wout;
    cudaGetSymbolAddress(&p_normed, g_normed_h);
    cudaGetSymbolAddress(&p_qkv, g_qkv_h);
    cudaGetSymbolAddress(&p_ao, g_ao_h);
    cudaGetSymbolAddress(&p_wqkv, g_wqkv_h);
    cudaGetSymbolAddress(&p_wout, g_wout_h);
    __half* normed = (__half*)p_normed;
    __half* qkv = (__half*)p_qkv;
    __half* ao = (__half*)p_ao;
    __half* wqkv = (__half*)p_wqkv;
    __half* wout = (__half*)p_wout;

    // weight conversions (independent of everything else)
    conv_kernel<<<(DF * QKV3) / 1024, 256>>>(w_qkv, wqkv);
    conv_kernel<<<(ID * DF) / 1024, 256>>>(w_out, wout);
    // 1) ball query
    ball_kernel<<<dim3(NP / 64, BQ), 256>>>(xyzs);
    // 2) layernorm -> fp16
    ln_kernel<<<(BQ * NP) / 8, 256>>>(feature, ln_g, ln_b);
    // 3) qkv = normed @ w_qkv   [32768 x 256] @ [256 x 1536] -> fp16
    hgemm_kernel<0><<<dim3(QKV3 / 128, (BQ * NP) / 128), 256>>>(
        normed, wqkv, qkv, QKV3, DF, nullptr, nullptr);
    // 4) attention + spatial op -> g_ao (fp16)
    attn_kernel<<<BQ * NP, 256>>>(xyzs, w_sp);
    // 5) out = gelu(ao @ w_out + b_out) + feature   [32768 x 512] @ [512 x 256] -> fp32
    hgemm_kernel<1><<<dim3(DF / 128, (BQ * NP) / 128), 256>>>(
        ao, wout, out, DF, ID, b_out, feature);
}